// round 15
// baseline (speedup 1.0000x reference)
#include <cuda_runtime.h>
#include <cuda_fp16.h>
#include <cstdint>

#define H_   32
#define W_   32
#define C_   512
#define CLS_ 1000
#define R_   64
#define B_   128
#define MROWS (B_ * C_)      // 65536
#define KDIM  1024           // W*H

// ---- GEMM tiling ----
#define TILE_M   128
#define KCHUNK   64          // fp16 per row = 128 B (one swizzle atom row)
#define KSPLIT   2           // K halves -> 2 CTAs per m-tile
#define NCHUNKS  8           // (KDIM/KSPLIT)/KCHUNK
// smem layout (bytes): A stage0 16K | A stage1 16K | B 64K (8 chunk-tiles x 8K)
#define A_OFF    0
#define ASTAGE   16384
#define B_OFF    32768
#define BCHUNK   8192
#define SMEM_DYN (32768 + 65536)   // 96 KB

#define SW(o) ((o) ^ (((o) >> 3) & 0x70))

// ---- static device scratch (no allocations allowed) ----
__device__ float g_part[1024 * R_];               // per-CTA partials

// ===========================================================================
// PTX helpers — sm_80+ baseline only
// ===========================================================================
__device__ __forceinline__ uint32_t smem_u32(const void* p) {
    uint32_t a;
    asm("{ .reg .u64 t; cvta.to.shared.u64 t, %1; cvt.u32.u64 %0, t; }"
        : "=r"(a) : "l"(p));
    return a;
}
__device__ __forceinline__ void sts64(uint32_t a, uint32_t x, uint32_t y) {
    asm volatile("st.shared.v2.b32 [%0], {%1,%2};" :: "r"(a), "r"(x), "r"(y));
}
__device__ __forceinline__ void sts128(uint32_t a, uint32_t x, uint32_t y,
                                       uint32_t z, uint32_t w) {
    asm volatile("st.shared.v4.b32 [%0], {%1,%2,%3,%4};"
                 :: "r"(a), "r"(x), "r"(y), "r"(z), "r"(w));
}
__device__ __forceinline__ void ldm4(uint32_t* r, uint32_t addr) {
    asm volatile("ldmatrix.sync.aligned.m8n8.x4.shared.b16 {%0,%1,%2,%3}, [%4];"
                 : "=r"(r[0]), "=r"(r[1]), "=r"(r[2]), "=r"(r[3]) : "r"(addr));
}
__device__ __forceinline__ void mma16816(float* c, const uint32_t* a, const uint32_t* b) {
    asm volatile(
        "mma.sync.aligned.m16n8k16.row.col.f32.f16.f16.f32 "
        "{%0,%1,%2,%3}, {%4,%5,%6,%7}, {%8,%9}, {%0,%1,%2,%3};"
        : "+f"(c[0]), "+f"(c[1]), "+f"(c[2]), "+f"(c[3])
        : "r"(a[0]), "r"(a[1]), "r"(a[2]), "r"(a[3]), "r"(b[0]), "r"(b[1]));
}
__device__ __forceinline__ uint32_t packh2(float a, float b) {
    __half2 h = __floats2half2_rn(a, b);
    return *reinterpret_cast<uint32_t*>(&h);
}

// ===========================================================================
// Kernel 1: pipelined fp16 mma.sync GEMM + fused U3 row-reduce, K-split x2.
//   B generated in-CTA once (no build_M kernel, no per-chunk cp.async).
//   grid 1024 (= 512 m-tiles x 2 K-halves), block 256, dyn smem 96K.
// ===========================================================================
__global__ __launch_bounds__(256, 2) void gemm_k(const float* __restrict__ x,
                                                 const float* __restrict__ U1,
                                                 const float* __restrict__ U2,
                                                 const float* __restrict__ U3) {
    extern __shared__ char dsm[];
    __shared__ float s_red[4][R_];

    const int tid  = threadIdx.x;
    const int wid  = tid >> 5;
    const int lane = tid & 31;
    const int m_warp = (wid >> 1) * 32;   // 0,32,64,96
    const int n_warp = (wid & 1) * 32;    // 0,32
    const int mt    = blockIdx.x >> 1;    // m-tile 0..511
    const int kbase = (blockIdx.x & 1) * (KDIM / KSPLIT);   // 0 or 512
    const int wbase = kbase >> 5;                            // 0 or 16
    const long m0 = (long)mt * TILE_M;

    const uint32_t sb = smem_u32(dsm);

    const int rb = tid >> 4;            // 0..15
    const int f  = tid & 15;            // 0..15

    // ---- start A chunk 0 LDG first (longest latency path) ----
    float4 pf[8];
    {
        const float* xg = x + m0 * KDIM + kbase;
#pragma unroll
        for (int it = 0; it < 8; it++)
            pf[it] = *(const float4*)(xg + (long)(rb + it * 16) * KDIM + f * 4);
    }

    // ---- load U1/U2 transposed into A-area smem (stride 33 pad) ----
    // su1T[r][h] at float offset r*33+h; su2T likewise at +2176 floats.
    float* su1T = (float*)dsm;                    // 64*33*4 = 8448 B
    float* su2T = (float*)dsm + 2176;             // another 8448 B (< 32 KB A area)
#pragma unroll
    for (int it = 0; it < 8; it++) {
        int i = tid + it * 256;                   // 0..2047 = h*64+r
        int hh = i >> 6, rr = i & 63;
        su1T[rr * 33 + hh] = U1[i];
        su2T[rr * 33 + hh] = U2[i];
    }
    __syncthreads();

    // ---- generate B once: 8 chunk-tiles, swizzled ----
    // thread -> n-row = tid>>2 (0..63), quarter q = tid&3 (16 k each).
    {
        const int n = tid >> 2;
        const int q = tid & 3;
        const int h0 = (q & 1) * 16;              // h range start
        const float* u1p = &su1T[n * 33 + h0];
#pragma unroll
        for (int s = 0; s < NCHUNKS; s++) {
            const int w = wbase + 2 * s + (q >> 1);
            const float u2v = su2T[n * 33 + (w - wbase) + wbase * 0 + (kbase ? 16 : 0) * 0 + 0 + (w & 31) * 0 + (w - (wbase + 2 * s + (q >> 1))) * 0 + ((2 * s + (q >> 1)) - (2 * s + (q >> 1))) * 0 + (w >= 0 ? 0 : 0)];
            // (simplified below — index is just global w)
            const float u2 = su2T[n * 33 + w];
            uint32_t p0 = packh2(u2 * u1p[0],  u2 * u1p[1]);
            uint32_t p1 = packh2(u2 * u1p[2],  u2 * u1p[3]);
            uint32_t p2 = packh2(u2 * u1p[4],  u2 * u1p[5]);
            uint32_t p3 = packh2(u2 * u1p[6],  u2 * u1p[7]);
            uint32_t p4 = packh2(u2 * u1p[8],  u2 * u1p[9]);
            uint32_t p5 = packh2(u2 * u1p[10], u2 * u1p[11]);
            uint32_t p6 = packh2(u2 * u1p[12], u2 * u1p[13]);
            uint32_t p7 = packh2(u2 * u1p[14], u2 * u1p[15]);
            uint32_t base = (uint32_t)(n * 128 + q * 32);
            uint32_t t0 = sb + B_OFF + s * BCHUNK + SW(base);
            uint32_t t1 = sb + B_OFF + s * BCHUNK + SW(base + 16);
            sts128(t0, p0, p1, p2, p3);
            sts128(t1, p4, p5, p6, p7);
            (void)u2v;
        }
    }
    __syncthreads();   // B ready; A area free for chunk STS

    float acc[2][4][4];
#pragma unroll
    for (int i = 0; i < 2; i++)
#pragma unroll
        for (int j = 0; j < 4; j++)
#pragma unroll
            for (int e = 0; e < 4; e++) acc[i][j][e] = 0.0f;

    for (int s = 0; s < NCHUNKS; s++) {
        const uint32_t ba = sb + A_OFF + (uint32_t)(s & 1) * ASTAGE;
        const uint32_t bB = sb + B_OFF + (uint32_t)s * BCHUNK;

        // ---- convert prefetched A regs -> fp16 swizzled smem (stage s%2;
        //      last read by MMA(s-2), ordered by barrier(s-1)) ----
#pragma unroll
        for (int it = 0; it < 8; it++) {
            float4 v = pf[it];
            uint32_t hA = packh2(v.x, v.y);
            uint32_t hB = packh2(v.z, v.w);
            uint32_t sw = SW((uint32_t)((rb + it * 16) * 128 + f * 8));
            sts64(ba + sw, hA, hB);
        }

        // ---- issue A LDG for chunk s+1 (completes under MMA) ----
        if (s < NCHUNKS - 1) {
            const float* xg = x + m0 * KDIM + kbase + (s + 1) * KCHUNK;
#pragma unroll
            for (int it = 0; it < 8; it++)
                pf[it] = *(const float4*)(xg + (long)(rb + it * 16) * KDIM + f * 4);
        }

        __syncthreads();     // STS(s) visible; MMA(s-1) complete everywhere

        // ---- compute: 4 k16-steps ----
#pragma unroll
        for (int kk = 0; kk < 4; kk++) {
            uint32_t ah[2][4], bhh[2][4];
#pragma unroll
            for (int mi = 0; mi < 2; mi++) {
                uint32_t row = m_warp + mi * 16 + (lane & 15);
                uint32_t kb  = kk * 32 + (lane >> 4) * 16;
                ldm4(ah[mi], ba + SW(row * 128 + kb));
            }
#pragma unroll
            for (int nq = 0; nq < 2; nq++) {
                uint32_t g = lane >> 3;
                uint32_t n = n_warp + nq * 16 + ((g >> 1) << 3) + (lane & 7);
                uint32_t kb = kk * 32 + (g & 1) * 16;
                ldm4(bhh[nq], bB + SW(n * 128 + kb));
            }
#pragma unroll
            for (int mi = 0; mi < 2; mi++)
#pragma unroll
                for (int nj = 0; nj < 4; nj++)
                    mma16816(acc[mi][nj], ah[mi], &bhh[nj >> 1][(nj & 1) * 2]);
        }
        // single barrier per chunk — next iteration's barrier provides the
        // write-after-read protection for A stage s%2.  B is read-only.
    }
    __syncthreads();   // MMA(7) (reads A stage 1) done before s_u3 overwrite

    // ---- epilogue: scale by U3[c,r], reduce 128 rows -> 64 partials ----
    float* s_u3 = (float*)dsm;                     // 32 KB A area
    const int c_base = (mt & 3) * 128;
#pragma unroll
    for (int it = 0; it < 32; it++) {
        int idx = tid + it * 256;                  // 0..8191
        s_u3[idx] = U3[c_base * R_ + idx];
    }
    __syncthreads();

    float p[8];
#pragma unroll
    for (int j = 0; j < 8; j++) p[j] = 0.0f;
#pragma unroll
    for (int mi = 0; mi < 2; mi++)
#pragma unroll
        for (int pr = 0; pr < 2; pr++) {
            int rowl = m_warp + mi * 16 + pr * 8 + (lane >> 2);
            const float* w = s_u3 + rowl * R_;
#pragma unroll
            for (int nj = 0; nj < 4; nj++) {
                int col = n_warp + nj * 8 + (lane & 3) * 2;
                p[nj * 2 + 0] = fmaf(acc[mi][nj][pr * 2 + 0], w[col],     p[nj * 2 + 0]);
                p[nj * 2 + 1] = fmaf(acc[mi][nj][pr * 2 + 1], w[col + 1], p[nj * 2 + 1]);
            }
        }
#pragma unroll
    for (int o = 4; o < 32; o <<= 1)
#pragma unroll
        for (int j = 0; j < 8; j++)
            p[j] += __shfl_xor_sync(0xffffffffu, p[j], o);

    if (lane < 4) {
#pragma unroll
        for (int nj = 0; nj < 4; nj++) {
            int col = n_warp + nj * 8 + lane * 2;
            s_red[wid >> 1][col]     = p[nj * 2 + 0];
            s_red[wid >> 1][col + 1] = p[nj * 2 + 1];
        }
    }
    __syncthreads();
    if (tid < R_)
        g_part[blockIdx.x * R_ + tid] =
            s_red[0][tid] + s_red[1][tid] + s_red[2][tid] + s_red[3][tid];
}

// ===========================================================================
// Kernel 2: out[b,cls] = sum_r (sum_{j<8} part[8b+j,r]) * lam[r] * U4[cls,r]
//   grid 1024 = 8 class-chunks x 128 b, block 128: one class per thread.
// ===========================================================================
__global__ __launch_bounds__(128) void out_k(const float* __restrict__ lam,
                                             const float* __restrict__ U4,
                                             float* __restrict__ out) {
    const int b     = blockIdx.x & 127;     // 0..127
    const int chunk = blockIdx.x >> 7;      // 0..7
    const int tid   = threadIdx.x;

    __shared__ float u[R_];
    if (tid < R_) {
        float s = 0.0f;
#pragma unroll
        for (int j = 0; j < 8; j++)
            s += g_part[(b * 8 + j) * R_ + tid];
        u[tid] = s * lam[tid];
    }
    __syncthreads();

    const int cls = chunk * 125 + tid;      // 8 x 125 = 1000
    if (tid < 125) {
        const float4* up = (const float4*)(U4 + cls * R_);
        float s = 0.0f;
#pragma unroll
        for (int j = 0; j < 16; j++) {
            float4 v = up[j];
            s = fmaf(u[j * 4 + 0], v.x, s);
            s = fmaf(u[j * 4 + 1], v.y, s);
            s = fmaf(u[j * 4 + 2], v.z, s);
            s = fmaf(u[j * 4 + 3], v.w, s);
        }
        out[b * CLS_ + cls] = s;
    }
}

// ===========================================================================
extern "C" void kernel_launch(void* const* d_in, const int* in_sizes, int n_in,
                              void* d_out, int out_size) {
    const float* x   = (const float*)d_in[0];   // (B, C, W, H)
    const float* U1  = (const float*)d_in[1];   // (H, R)
    const float* U2  = (const float*)d_in[2];   // (W, R)
    const float* U3  = (const float*)d_in[3];   // (C, R)
    const float* U4  = (const float*)d_in[4];   // (CLS, R)
    const float* lam = (const float*)d_in[5];   // (R,)
    float* out = (float*)d_out;                 // (B, CLS)

    cudaFuncSetAttribute(gemm_k, cudaFuncAttributeMaxDynamicSharedMemorySize, SMEM_DYN);

    gemm_k<<<(MROWS / TILE_M) * KSPLIT, 256, SMEM_DYN>>>(x, U1, U2, U3);
    out_k<<<1024, 128>>>(lam, U4, out);
}